// round 5
// baseline (speedup 1.0000x reference)
#include <cuda_runtime.h>
#include <cstdint>
#include <cstddef>

// Problem constants
#define Bb 64
#define Tt 2048
#define Ii 128
#define Hh 256
#define Oo 128
#define Mm 256   // H - K1 + 1

// ---------------- scratch (device globals; no allocation allowed) ----------------
__device__ float g_uhats[Mm * Hh];
__device__ float g_vhats[Mm * Hh];
__device__ float g_bu[Mm];
__device__ float g_bv[Mm];
__device__ float g_U[Hh * Hh];
__device__ float g_V[Hh * Hh];
__device__ float g_W[Hh * Hh];
__device__ float g_xproj[(size_t)Bb * Tt * Hh];  // [B,T,H]
__device__ float g_hall [(size_t)Bb * Tt * Hh];  // [B,T,H]

// ---------------- helpers ----------------
__device__ __forceinline__ unsigned smem_u32(const void* p) {
    return (unsigned)__cvta_generic_to_shared(p);
}

// mbarrier parity wait, acquire at cluster scope (observes peer DSMEM stores).
__device__ __forceinline__ void mbar_wait_cluster(unsigned addr, unsigned phase) {
    unsigned done;
    asm volatile(
        "{\n\t.reg .pred p;\n\t"
        "mbarrier.try_wait.parity.acquire.cluster.shared::cta.b64 p, [%1], %2;\n\t"
        "selp.b32 %0, 1, 0, p;\n\t}"
        : "=r"(done) : "r"(addr), "r"(phase) : "memory");
    while (!done) {
        asm volatile(
            "{\n\t.reg .pred p;\n\t"
            "mbarrier.try_wait.parity.acquire.cluster.shared::cta.b64 p, [%1], %2;\n\t"
            "selp.b32 %0, 1, 0, p;\n\t}"
            : "=r"(done) : "r"(addr), "r"(phase) : "memory");
    }
}

// ============================================================================
// Kernel 1: build u_hats / v_hats (mask + flips) and betas = 2/<u,u>
// ============================================================================
__global__ __launch_bounds__(256) void prep_kernel(const float* __restrict__ u_raw,
                                                   const float* __restrict__ v_raw) {
    __shared__ float red[256];
    int i = blockIdx.x & 255;
    bool isv = blockIdx.x >= 256;
    int j = threadIdx.x;
    float val = 0.f;
    if (!isv) {
        if (j >= 255 - i) val = u_raw[i * Hh + (255 - j)];
        g_uhats[i * Hh + j] = val;
    } else {
        if (j >= i) val = v_raw[(255 - i) * Hh + (255 - j)];
        g_vhats[i * Hh + j] = val;
    }
    red[j] = val * val;
    __syncthreads();
    for (int s = 128; s > 0; s >>= 1) {
        if (j < s) red[j] += red[j + s];
        __syncthreads();
    }
    if (j == 0) {
        float beta = 2.f / red[0];
        if (isv) g_bv[i] = beta; else g_bu[i] = beta;
    }
}

// ============================================================================
// Kernel 2: Householder chains, one warp per column of U/V.
// ============================================================================
__global__ __launch_bounds__(256) void chain_kernel() {
    int warp = (blockIdx.x * blockDim.x + threadIdx.x) >> 5;
    int lane = threadIdx.x & 31;
    int col = warp & 255;
    bool isv = warp >= 256;
    const float* hats  = isv ? g_vhats : g_uhats;
    const float* betas = isv ? g_bv    : g_bu;
    float* out         = isv ? g_V     : g_U;

    float c[8];
#pragma unroll
    for (int q = 0; q < 8; q++) c[q] = ((lane + 32 * q) == col) ? 1.f : 0.f;

    for (int i = 0; i < Mm; i++) {
        float u[8];
#pragma unroll
        for (int q = 0; q < 8; q++) u[q] = hats[i * Hh + lane + 32 * q];
        float s = 0.f;
#pragma unroll
        for (int q = 0; q < 8; q++) s = fmaf(u[q], c[q], s);
#pragma unroll
        for (int off = 16; off > 0; off >>= 1)
            s += __shfl_xor_sync(0xffffffffu, s, off);
        float sc = betas[i] * s;
#pragma unroll
        for (int q = 0; q < 8; q++) c[q] = fmaf(-sc, u[q], c[q]);
    }
#pragma unroll
    for (int q = 0; q < 8; q++) out[(size_t)(lane + 32 * q) * Hh + col] = c[q];
}

// ============================================================================
// Kernel 3: W = (U * diag(sigmas)) @ V.
// ============================================================================
__global__ __launch_bounds__(256) void wgemm_kernel(const float* __restrict__ sig) {
    __shared__ float su[Hh];
    int r = blockIdx.x;
    int cidx = threadIdx.x;
    su[cidx] = g_U[r * Hh + cidx] * sig[cidx];
    __syncthreads();
    float acc = 0.f;
#pragma unroll 8
    for (int k = 0; k < Hh; k++) acc = fmaf(su[k], g_V[(size_t)k * Hh + cidx], acc);
    g_W[r * Hh + cidx] = acc;
}

// ============================================================================
// Kernel 4/6: SGEMM  C[MxN] = A[MxK] * B[NxK]^T + bias[N]   (R2-exact version)
// 128x128 block tile, 8x8 per thread, BK=16, 256 threads.
// ============================================================================
__global__ __launch_bounds__(256) void sgemm_nt(const float* __restrict__ A,
                                                const float* __restrict__ Bm,
                                                const float* __restrict__ bias,
                                                float* __restrict__ C,
                                                int M, int N, int K) {
    __shared__ float As[16][128];
    __shared__ float Bs[16][128];
    int tid = threadIdx.x;
    int m0 = blockIdx.y * 128;
    int n0 = blockIdx.x * 128;
    int tx = tid & 15;   // n
    int ty = tid >> 4;   // m

    float acc[8][8];
#pragma unroll
    for (int i = 0; i < 8; i++)
#pragma unroll
        for (int j = 0; j < 8; j++) acc[i][j] = 0.f;

    for (int k0 = 0; k0 < K; k0 += 16) {
#pragma unroll
        for (int i = 0; i < 2; i++) {
            int fid = tid + i * 256;          // 0..511
            int row = fid >> 2;               // 0..127
            int c4  = fid & 3;                // 0..3
            float4 va = *(const float4*)(A  + (size_t)(m0 + row) * K + k0 + c4 * 4);
            As[c4 * 4 + 0][row] = va.x; As[c4 * 4 + 1][row] = va.y;
            As[c4 * 4 + 2][row] = va.z; As[c4 * 4 + 3][row] = va.w;
            float4 vb = *(const float4*)(Bm + (size_t)(n0 + row) * K + k0 + c4 * 4);
            Bs[c4 * 4 + 0][row] = vb.x; Bs[c4 * 4 + 1][row] = vb.y;
            Bs[c4 * 4 + 2][row] = vb.z; Bs[c4 * 4 + 3][row] = vb.w;
        }
        __syncthreads();
#pragma unroll
        for (int kk = 0; kk < 16; kk++) {
            float a[8], b[8];
            *(float4*)(a)     = *(const float4*)&As[kk][ty * 8];
            *(float4*)(a + 4) = *(const float4*)&As[kk][ty * 8 + 4];
            *(float4*)(b)     = *(const float4*)&Bs[kk][tx * 8];
            *(float4*)(b + 4) = *(const float4*)&Bs[kk][tx * 8 + 4];
#pragma unroll
            for (int i = 0; i < 8; i++)
#pragma unroll
                for (int j = 0; j < 8; j++)
                    acc[i][j] = fmaf(a[i], b[j], acc[i][j]);
        }
        __syncthreads();
    }

    float bv[8];
#pragma unroll
    for (int j = 0; j < 8; j++) bv[j] = bias[n0 + tx * 8 + j];
#pragma unroll
    for (int i = 0; i < 8; i++) {
        size_t base = (size_t)(m0 + ty * 8 + i) * N + n0 + tx * 8;
        float4 o0, o1;
        o0.x = acc[i][0] + bv[0]; o0.y = acc[i][1] + bv[1];
        o0.z = acc[i][2] + bv[2]; o0.w = acc[i][3] + bv[3];
        o1.x = acc[i][4] + bv[4]; o1.y = acc[i][5] + bv[5];
        o1.z = acc[i][6] + bv[6]; o1.w = acc[i][7] + bv[7];
        *(float4*)(C + base)     = o0;
        *(float4*)(C + base + 4) = o1;
    }
}

// ============================================================================
// Kernel 5: recurrence. 2-CTA cluster per batch, 256 threads/CTA.
//
// Work split (per CTA, rows half*128..half*128+127):
//   warp w (0..7): k-slice [32w, 32w+32)  -> h loads are warp-uniform (LDS broadcast)
//   lane l: 4 rows  half*128 + 4l + {0..3};  W slice = 128 regs (4x8 float4)
// Cross-warp reduce via double-buffered smem partials + 1 __syncthreads.
// Threads 0..127 finalize row r=tid: sum 8 partials + xproj, tanh, write
// local hbuf + DSMEM push to peer + gmem hall (output GEMM deferred).
//
// Sync: two mbarriers per CTA, mb[s] guards h-half s of hbuf[next].
//   Writers (warps 0..3): after __syncwarp, lane0 arrives on own mb[half]
//   (release.cluster) and on peer's mb[half] (remote, release.cluster).
//   Warp w waits on mb[w>>2] with parity (t-1)&1 before reading hbuf[cur].
// -> warps consuming the locally-produced half never wait on the peer;
//    peer-half latency (~215cyc DSMEM) overlaps local warps' FMA.
// No barrier.cluster in the loop (no 490cyc sync, no per-step L1D flush).
// ============================================================================
__global__ __launch_bounds__(256, 1) __cluster_dims__(2, 1, 1)
void rnn_kernel() {
    __shared__ float hbuf[2][256];
    __shared__ float part[2][8][128];
    __shared__ __align__(8) unsigned long long mb[2];

    unsigned rank;
    asm("mov.u32 %0, %%cluster_ctarank;" : "=r"(rank));
    int half = (int)rank;
    unsigned peer = rank ^ 1u;
    int b = blockIdx.x >> 1;
    int tid = threadIdx.x;
    int w = tid >> 5;
    int l = tid & 31;
    int hw = w >> 2;                 // which h-half this warp consumes

    // W registers: rows half*128 + 4l + j, k in [32w, 32w+32)
    float4 w4[4][8];
    {
        int row0 = half * 128 + l * 4;
#pragma unroll
        for (int j = 0; j < 4; j++) {
            const float4* wp = (const float4*)(g_W + (size_t)(row0 + j) * Hh + w * 32);
#pragma unroll
            for (int q = 0; q < 8; q++) w4[j][q] = wp[q];
        }
    }

    hbuf[0][tid] = 0.f;
    unsigned mb0 = smem_u32((const void*)&mb[0]);
    unsigned mb1 = smem_u32((const void*)&mb[1]);
    if (tid == 0) {
        asm volatile("mbarrier.init.shared.b64 [%0], %1;" :: "r"(mb0), "r"(4u) : "memory");
        asm volatile("mbarrier.init.shared.b64 [%0], %1;" :: "r"(mb1), "r"(4u) : "memory");
    }
    __syncthreads();
    // one-time cluster sync: mbarrier init + hbuf[0]=0 visible cluster-wide
    asm volatile("barrier.cluster.arrive.aligned;" ::: "memory");
    asm volatile("barrier.cluster.wait.aligned;" ::: "memory");

    unsigned mb_wait  = (hw == 0) ? mb0 : mb1;       // barrier this warp waits on
    unsigned mb_write = (half == 0) ? mb0 : mb1;     // barrier writers arrive on

    // finalizer-side pointers (threads 0..127, row r = tid)
    int growf = half * 128 + tid;
    const float* xp_ptr   = g_xproj + (size_t)b * Tt * Hh + growf;
    float*       hall_ptr = g_hall  + (size_t)b * Tt * Hh + growf;
    float xp0 = 0.f, xp1 = 0.f;
    if (tid < 128) {
        xp0 = xp_ptr[0];
        xp1 = xp_ptr[Hh];
    }

    int cur = 0;
    unsigned ph = 0;
    for (int t = 0; t < Tt; t++) {
        int pp = t & 1;
        float xp2 = 0.f;
        if (tid < 128 && (t + 2) < Tt) xp2 = xp_ptr[(size_t)(t + 2) * Hh];

        if (t > 0) {                       // hbuf[0] pre-zeroed for t=0
            mbar_wait_cluster(mb_wait, ph);
            ph ^= 1u;
        }

        // partial mat-vec: 4 rows x 32 k, h loads warp-uniform (broadcast)
        const float4* hp = (const float4*)&hbuf[cur][w * 32];
        float a0 = 0.f, a1 = 0.f, a2 = 0.f, a3 = 0.f;
#pragma unroll
        for (int q = 0; q < 8; q++) {
            float4 hv = hp[q];
            a0 = fmaf(w4[0][q].x, hv.x, a0); a0 = fmaf(w4[0][q].y, hv.y, a0);
            a0 = fmaf(w4[0][q].z, hv.z, a0); a0 = fmaf(w4[0][q].w, hv.w, a0);
            a1 = fmaf(w4[1][q].x, hv.x, a1); a1 = fmaf(w4[1][q].y, hv.y, a1);
            a1 = fmaf(w4[1][q].z, hv.z, a1); a1 = fmaf(w4[1][q].w, hv.w, a1);
            a2 = fmaf(w4[2][q].x, hv.x, a2); a2 = fmaf(w4[2][q].y, hv.y, a2);
            a2 = fmaf(w4[2][q].z, hv.z, a2); a2 = fmaf(w4[2][q].w, hv.w, a2);
            a3 = fmaf(w4[3][q].x, hv.x, a3); a3 = fmaf(w4[3][q].y, hv.y, a3);
            a3 = fmaf(w4[3][q].z, hv.z, a3); a3 = fmaf(w4[3][q].w, hv.w, a3);
        }
        *(float4*)&part[pp][w][l * 4] = make_float4(a0, a1, a2, a3);
        __syncthreads();

        int nxt = cur ^ 1;
        if (tid < 128) {
            float s = ((part[pp][0][tid] + part[pp][1][tid]) +
                       (part[pp][2][tid] + part[pp][3][tid])) +
                      ((part[pp][4][tid] + part[pp][5][tid]) +
                       (part[pp][6][tid] + part[pp][7][tid])) + xp0;
            float v = tanhf(s);
            hbuf[nxt][growf] = v;                         // local copy
            unsigned la = smem_u32(&hbuf[nxt][growf]);
            asm volatile(                                  // push to peer
                "{\n\t.reg .b32 ra;\n\t"
                "mapa.shared::cluster.u32 ra, %0, %1;\n\t"
                "st.shared::cluster.f32 [ra], %2;\n\t}"
                :: "r"(la), "r"(peer), "f"(v) : "memory");
            hall_ptr[(size_t)t * Hh] = v;                 // deferred out-proj
            xp0 = xp1; xp1 = xp2;
            __syncwarp();
            if (l == 0 && (t + 1) < Tt) {
                asm volatile(                              // local arrive
                    "mbarrier.arrive.release.cluster.shared::cta.b64 _, [%0];"
                    :: "r"(mb_write) : "memory");
                asm volatile(                              // remote arrive
                    "{\n\t.reg .b32 rb;\n\t"
                    "mapa.shared::cluster.u32 rb, %0, %1;\n\t"
                    "mbarrier.arrive.release.cluster.shared::cluster.b64 _, [rb];\n\t}"
                    :: "r"(mb_write), "r"(peer) : "memory");
            }
        }
        cur = nxt;
    }

    // keep SMEM alive until all inbound remote ops are done
    asm volatile("barrier.cluster.arrive.aligned;" ::: "memory");
    asm volatile("barrier.cluster.wait.aligned;" ::: "memory");
}

// ============================================================================
// launch
// ============================================================================
extern "C" void kernel_launch(void* const* d_in, const int* in_sizes, int n_in,
                              void* d_out, int out_size) {
    const float* x      = (const float*)d_in[0];
    const float* W_in   = (const float*)d_in[1];
    const float* b_in   = (const float*)d_in[2];
    const float* W_out  = (const float*)d_in[3];
    const float* b_out  = (const float*)d_in[4];
    const float* u_raw  = (const float*)d_in[5];
    const float* sigmas = (const float*)d_in[6];
    const float* v_raw  = (const float*)d_in[7];
    float* out = (float*)d_out;

    void* xp_v = nullptr;
    void* hall_v = nullptr;
    cudaGetSymbolAddress(&xp_v, g_xproj);
    cudaGetSymbolAddress(&hall_v, g_hall);
    float* xp = (float*)xp_v;
    float* hall = (float*)hall_v;

    prep_kernel<<<512, 256>>>(u_raw, v_raw);
    chain_kernel<<<64, 256>>>();
    wgemm_kernel<<<256, 256>>>(sigmas);
    sgemm_nt<<<dim3(Hh / 128, (Bb * Tt) / 128), 256>>>(x, W_in, b_in, xp,
                                                       Bb * Tt, Hh, Ii);
    rnn_kernel<<<Bb * 2, 256>>>();
    sgemm_nt<<<dim3(Oo / 128, (Bb * Tt) / 128), 256>>>(hall, W_out, b_out, out,
                                                       Bb * Tt, Oo, Hh);
}

// round 7
// speedup vs baseline: 1.5256x; 1.5256x over previous
#include <cuda_runtime.h>
#include <cstdint>
#include <cstddef>

// Problem constants
#define Bb 64
#define Tt 2048
#define Ii 128
#define Hh 256
#define Oo 128
#define Mm 256   // H - K1 + 1

// ---------------- scratch (device globals; no allocation allowed) ----------------
__device__ float g_uhats[Mm * Hh];
__device__ float g_vhats[Mm * Hh];
__device__ float g_bu[Mm];
__device__ float g_bv[Mm];
__device__ float g_U[Hh * Hh];
__device__ float g_V[Hh * Hh];
__device__ float g_W[Hh * Hh];
__device__ float g_xproj[(size_t)Bb * Tt * Hh];  // [B,T,H]
__device__ float g_hall [(size_t)Bb * Tt * Hh];  // [B,T,H]

// ---------------- packed f32x2 helpers ----------------
__device__ __forceinline__ unsigned long long pack2(float lo, float hi) {
    unsigned long long r;
    asm("mov.b64 %0, {%1, %2};" : "=l"(r) : "f"(lo), "f"(hi));
    return r;
}
__device__ __forceinline__ void fma2(unsigned long long& d,
                                     unsigned long long a,
                                     unsigned long long b) {
    asm("fma.rn.f32x2 %0, %1, %2, %0;" : "+l"(d) : "l"(a), "l"(b));
}
__device__ __forceinline__ float2 unpack2(unsigned long long v) {
    float lo, hi;
    asm("mov.b64 {%0, %1}, %2;" : "=f"(lo), "=f"(hi) : "l"(v));
    return make_float2(lo, hi);
}

// ============================================================================
// Kernel 1: build u_hats / v_hats (mask + flips) and betas = 2/<u,u>
// ============================================================================
__global__ __launch_bounds__(256) void prep_kernel(const float* __restrict__ u_raw,
                                                   const float* __restrict__ v_raw) {
    __shared__ float red[256];
    int i = blockIdx.x & 255;
    bool isv = blockIdx.x >= 256;
    int j = threadIdx.x;
    float val = 0.f;
    if (!isv) {
        if (j >= 255 - i) val = u_raw[i * Hh + (255 - j)];
        g_uhats[i * Hh + j] = val;
    } else {
        if (j >= i) val = v_raw[(255 - i) * Hh + (255 - j)];
        g_vhats[i * Hh + j] = val;
    }
    red[j] = val * val;
    __syncthreads();
    for (int s = 128; s > 0; s >>= 1) {
        if (j < s) red[j] += red[j + s];
        __syncthreads();
    }
    if (j == 0) {
        float beta = 2.f / red[0];
        if (isv) g_bv[i] = beta; else g_bu[i] = beta;
    }
}

// ============================================================================
// Kernel 2: Householder chains, one warp per column of U/V.
// ============================================================================
__global__ __launch_bounds__(256) void chain_kernel() {
    int warp = (blockIdx.x * blockDim.x + threadIdx.x) >> 5;
    int lane = threadIdx.x & 31;
    int col = warp & 255;
    bool isv = warp >= 256;
    const float* hats  = isv ? g_vhats : g_uhats;
    const float* betas = isv ? g_bv    : g_bu;
    float* out         = isv ? g_V     : g_U;

    float c[8];
#pragma unroll
    for (int q = 0; q < 8; q++) c[q] = ((lane + 32 * q) == col) ? 1.f : 0.f;

    for (int i = 0; i < Mm; i++) {
        float u[8];
#pragma unroll
        for (int q = 0; q < 8; q++) u[q] = hats[i * Hh + lane + 32 * q];
        float s = 0.f;
#pragma unroll
        for (int q = 0; q < 8; q++) s = fmaf(u[q], c[q], s);
#pragma unroll
        for (int off = 16; off > 0; off >>= 1)
            s += __shfl_xor_sync(0xffffffffu, s, off);
        float sc = betas[i] * s;
#pragma unroll
        for (int q = 0; q < 8; q++) c[q] = fmaf(-sc, u[q], c[q]);
    }
#pragma unroll
    for (int q = 0; q < 8; q++) out[(size_t)(lane + 32 * q) * Hh + col] = c[q];
}

// ============================================================================
// Kernel 3: W = (U * diag(sigmas)) @ V.
// ============================================================================
__global__ __launch_bounds__(256) void wgemm_kernel(const float* __restrict__ sig) {
    __shared__ float su[Hh];
    int r = blockIdx.x;
    int cidx = threadIdx.x;
    su[cidx] = g_U[r * Hh + cidx] * sig[cidx];
    __syncthreads();
    float acc = 0.f;
#pragma unroll 8
    for (int k = 0; k < Hh; k++) acc = fmaf(su[k], g_V[(size_t)k * Hh + cidx], acc);
    g_W[r * Hh + cidx] = acc;
}

// ============================================================================
// Kernel 4/6: SGEMM  C[MxN] = A[MxK] * B[NxK]^T + bias[N]   (R2-exact version)
// ============================================================================
__global__ __launch_bounds__(256) void sgemm_nt(const float* __restrict__ A,
                                                const float* __restrict__ Bm,
                                                const float* __restrict__ bias,
                                                float* __restrict__ C,
                                                int M, int N, int K) {
    __shared__ float As[16][128];
    __shared__ float Bs[16][128];
    int tid = threadIdx.x;
    int m0 = blockIdx.y * 128;
    int n0 = blockIdx.x * 128;
    int tx = tid & 15;
    int ty = tid >> 4;

    float acc[8][8];
#pragma unroll
    for (int i = 0; i < 8; i++)
#pragma unroll
        for (int j = 0; j < 8; j++) acc[i][j] = 0.f;

    for (int k0 = 0; k0 < K; k0 += 16) {
#pragma unroll
        for (int i = 0; i < 2; i++) {
            int fid = tid + i * 256;
            int row = fid >> 2;
            int c4  = fid & 3;
            float4 va = *(const float4*)(A  + (size_t)(m0 + row) * K + k0 + c4 * 4);
            As[c4 * 4 + 0][row] = va.x; As[c4 * 4 + 1][row] = va.y;
            As[c4 * 4 + 2][row] = va.z; As[c4 * 4 + 3][row] = va.w;
            float4 vb = *(const float4*)(Bm + (size_t)(n0 + row) * K + k0 + c4 * 4);
            Bs[c4 * 4 + 0][row] = vb.x; Bs[c4 * 4 + 1][row] = vb.y;
            Bs[c4 * 4 + 2][row] = vb.z; Bs[c4 * 4 + 3][row] = vb.w;
        }
        __syncthreads();
#pragma unroll
        for (int kk = 0; kk < 16; kk++) {
            float a[8], b[8];
            *(float4*)(a)     = *(const float4*)&As[kk][ty * 8];
            *(float4*)(a + 4) = *(const float4*)&As[kk][ty * 8 + 4];
            *(float4*)(b)     = *(const float4*)&Bs[kk][tx * 8];
            *(float4*)(b + 4) = *(const float4*)&Bs[kk][tx * 8 + 4];
#pragma unroll
            for (int i = 0; i < 8; i++)
#pragma unroll
                for (int j = 0; j < 8; j++)
                    acc[i][j] = fmaf(a[i], b[j], acc[i][j]);
        }
        __syncthreads();
    }

    float bv[8];
#pragma unroll
    for (int j = 0; j < 8; j++) bv[j] = bias[n0 + tx * 8 + j];
#pragma unroll
    for (int i = 0; i < 8; i++) {
        size_t base = (size_t)(m0 + ty * 8 + i) * N + n0 + tx * 8;
        float4 o0, o1;
        o0.x = acc[i][0] + bv[0]; o0.y = acc[i][1] + bv[1];
        o0.z = acc[i][2] + bv[2]; o0.w = acc[i][3] + bv[3];
        o1.x = acc[i][4] + bv[4]; o1.y = acc[i][5] + bv[5];
        o1.z = acc[i][6] + bv[6]; o1.w = acc[i][7] + bv[7];
        *(float4*)(C + base)     = o0;
        *(float4*)(C + base + 4) = o1;
    }
}

// ============================================================================
// Kernel 5: recurrence, SINGLE CTA per batch (no cluster, no DSMEM).
// 64 CTAs x 256 threads, occupancy 1 (register-heavy).
//
// Thread (warp w, lane l): kslice s = w&3 -> k in [64s, 64s+64)
//                          rowhalf rh = w>>2, rows r0..r0+3, r0 = 128*rh + 4*l
// W[row][k]: k in [64s, 64s+52) lives in 208 registers (packed f32x2),
//            k in [64s+52, 64s+64) lives in smem Ws[s][m][row] (m=0..11),
//            laid out so one LDS.128 fetches the 4 rows' weights for one m.
// Per step: rank-4 smem partial reduce (part[2][4][256]), 2 __syncthreads,
// every thread finalizes row = tid (tanh, h double-buffer, hall store,
// xproj depth-2 prefetch -- L1 stays warm, nothing flushes it).
// ============================================================================
#define WS_FLOATS   (4 * 12 * 256)                 // 12288
#define PART_OFF    WS_FLOATS                      // part[2][4][256] = 2048
#define HBUF_OFF    (PART_OFF + 2 * 4 * 256)       // hbuf[2][256]   = 512
#define RNN_SMEM_FLOATS (HBUF_OFF + 2 * 256)       // 14848
#define RNN_SMEM_BYTES  (RNN_SMEM_FLOATS * 4)      // 59392

__global__ __launch_bounds__(256) void rnn_solo() {
    extern __shared__ float dsm[];
    float* Ws   = dsm;                 // [4][12][256]
    float* part = dsm + PART_OFF;      // [2][4][256]
    float* hbuf = dsm + HBUF_OFF;      // [2][256]

    int b = blockIdx.x;
    int tid = threadIdx.x;
    int w = tid >> 5, l = tid & 31;
    int s = w & 3, rh = w >> 2;
    int r0 = 128 * rh + 4 * l;         // rows r0..r0+3
    int k0 = 64 * s;                   // k-slice base

    // ---- load W register slice: rows r0..r0+3, k in [k0, k0+52) ----
    unsigned long long w2[4][26];
#pragma unroll
    for (int j = 0; j < 4; j++) {
        const float4* wp = (const float4*)(g_W + (size_t)(r0 + j) * Hh + k0);
#pragma unroll
        for (int c = 0; c < 13; c++) {
            float4 v = wp[c];
            w2[j][2 * c]     = pack2(v.x, v.y);
            w2[j][2 * c + 1] = pack2(v.z, v.w);
        }
    }
    // ---- fill Ws[((ss*12)+mm)*256 + rr] = W[rr][64*ss + 52 + mm] ----
    for (int i = tid; i < WS_FLOATS; i += 256) {
        int grp = i / 256;             // 0..47  = ss*12 + mm
        int ss = grp / 12;             // 0..3   (FIX: was i>>12)
        int mm = grp % 12;             // 0..11
        int rr = i & 255;
        Ws[i] = g_W[(size_t)rr * Hh + 64 * ss + 52 + mm];
    }
    hbuf[tid] = 0.f;                   // hbuf[0]
    __syncthreads();

    // finalizer row = tid
    const float* xp_ptr   = g_xproj + (size_t)b * Tt * Hh + tid;
    float*       hall_ptr = g_hall  + (size_t)b * Tt * Hh + tid;
    float xp0 = xp_ptr[0];
    float xp1 = xp_ptr[Hh];

    int cur = 0;
    for (int t = 0; t < Tt; t++) {
        int pp = t & 1;
        float xp2 = 0.f;
        if (t + 2 < Tt) xp2 = xp_ptr[(size_t)(t + 2) * Hh];

        const float* h = hbuf + cur * 256 + k0;

        // register part: 26 packed fma2 per row
        unsigned long long a0 = 0ull, a1 = 0ull, a2 = 0ull, a3 = 0ull;
#pragma unroll
        for (int c = 0; c < 13; c++) {
            ulonglong2 hv = *(const ulonglong2*)(h + 4 * c);
            fma2(a0, w2[0][2 * c], hv.x); fma2(a0, w2[0][2 * c + 1], hv.y);
            fma2(a1, w2[1][2 * c], hv.x); fma2(a1, w2[1][2 * c + 1], hv.y);
            fma2(a2, w2[2][2 * c], hv.x); fma2(a2, w2[2][2 * c + 1], hv.y);
            fma2(a3, w2[3][2 * c], hv.x); fma2(a3, w2[3][2 * c + 1], hv.y);
        }

        // smem-W part: k = k0+52 .. k0+63
        float b0 = 0.f, b1 = 0.f, b2 = 0.f, b3 = 0.f;
#pragma unroll
        for (int c = 0; c < 3; c++) {
            float4 hf = *(const float4*)(h + 52 + 4 * c);
            float hs[4] = {hf.x, hf.y, hf.z, hf.w};
#pragma unroll
            for (int m2 = 0; m2 < 4; m2++) {
                int m = 4 * c + m2;
                float4 ws = *(const float4*)(Ws + (s * 12 + m) * 256 + r0);
                b0 = fmaf(ws.x, hs[m2], b0);
                b1 = fmaf(ws.y, hs[m2], b1);
                b2 = fmaf(ws.z, hs[m2], b2);
                b3 = fmaf(ws.w, hs[m2], b3);
            }
        }

        float2 p0 = unpack2(a0), p1 = unpack2(a1);
        float2 p2 = unpack2(a2), p3 = unpack2(a3);
        float4 o;
        o.x = p0.x + p0.y + b0;
        o.y = p1.x + p1.y + b1;
        o.z = p2.x + p2.y + b2;
        o.w = p3.x + p3.y + b3;
        *(float4*)(part + (pp * 4 + s) * 256 + r0) = o;
        __syncthreads();

        int nxt = cur ^ 1;
        const float* pb = part + pp * 1024 + tid;
        float sum = ((pb[0] + pb[256]) + (pb[512] + pb[768])) + xp0;
        float v = tanhf(sum);
        hbuf[nxt * 256 + tid] = v;
        hall_ptr[(size_t)t * Hh] = v;        // deferred output projection
        xp0 = xp1; xp1 = xp2;
        __syncthreads();
        cur = nxt;
    }
}

// ============================================================================
// launch
// ============================================================================
extern "C" void kernel_launch(void* const* d_in, const int* in_sizes, int n_in,
                              void* d_out, int out_size) {
    const float* x      = (const float*)d_in[0];
    const float* W_in   = (const float*)d_in[1];
    const float* b_in   = (const float*)d_in[2];
    const float* W_out  = (const float*)d_in[3];
    const float* b_out  = (const float*)d_in[4];
    const float* u_raw  = (const float*)d_in[5];
    const float* sigmas = (const float*)d_in[6];
    const float* v_raw  = (const float*)d_in[7];
    float* out = (float*)d_out;

    void* xp_v = nullptr;
    void* hall_v = nullptr;
    cudaGetSymbolAddress(&xp_v, g_xproj);
    cudaGetSymbolAddress(&hall_v, g_hall);
    float* xp = (float*)xp_v;
    float* hall = (float*)hall_v;

    cudaFuncSetAttribute(rnn_solo, cudaFuncAttributeMaxDynamicSharedMemorySize,
                         RNN_SMEM_BYTES);

    prep_kernel<<<512, 256>>>(u_raw, v_raw);
    chain_kernel<<<64, 256>>>();
    wgemm_kernel<<<256, 256>>>(sigmas);
    sgemm_nt<<<dim3(Hh / 128, (Bb * Tt) / 128), 256>>>(x, W_in, b_in, xp,
                                                       Bb * Tt, Hh, Ii);
    rnn_solo<<<Bb, 256, RNN_SMEM_BYTES>>>();
    sgemm_nt<<<dim3(Oo / 128, (Bb * Tt) / 128), 256>>>(hall, W_out, b_out, out,
                                                       Bb * Tt, Oo, Hh);
}